// round 13
// baseline (speedup 1.0000x reference)
#include <cuda_runtime.h>
#include <cuda_bf16.h>
#include <cstdint>
#include <cstddef>

typedef __nv_bfloat16 bf16;

#define NSEQ 2048
#define TT   32
#define EE   256
#define HH   512
#define MROWS (NSEQ*TT)

#define BM 128
#define BN 64
#define BK 32
#define BKP 40
#define NT 256

__device__ __align__(16) bf16  g_Ah[(size_t)MROWS * EE];
__device__ __align__(16) bf16  g_Al[(size_t)MROWS * EE];
__device__ __align__(16) float g_pre0[(size_t)TT * NSEQ * HH];
__device__ __align__(16) bf16  g_h0h[2][(size_t)NSEQ * HH];
__device__ __align__(16) bf16  g_h0l[2][(size_t)NSEQ * HH];
__device__ __align__(16) bf16  g_h1h[2][(size_t)NSEQ * HH];
__device__ __align__(16) bf16  g_h1l[2][(size_t)NSEQ * HH];
__device__ __align__(16) float g_h1f[(size_t)NSEQ * HH];

#define OFF_IH0 0
#define OFF_HH0 131072
#define OFF_IH1 393216
#define OFF_HH1 655360
#define WTOT    917504
__device__ __align__(16) bf16 g_Wh[WTOT];
__device__ __align__(16) bf16 g_Wl[WTOT];

__device__ __forceinline__ void ldsm4(uint32_t* r, uint32_t a) {
    asm volatile("ldmatrix.sync.aligned.m8n8.x4.shared.b16 {%0,%1,%2,%3},[%4];"
                 : "=r"(r[0]), "=r"(r[1]), "=r"(r[2]), "=r"(r[3]) : "r"(a));
}
__device__ __forceinline__ void ldsm2(uint32_t* r, uint32_t a) {
    asm volatile("ldmatrix.sync.aligned.m8n8.x2.shared.b16 {%0,%1},[%2];"
                 : "=r"(r[0]), "=r"(r[1]) : "r"(a));
}
__device__ __forceinline__ void mma16816(float* c, const uint32_t* a, const uint32_t* b) {
    asm volatile(
        "mma.sync.aligned.m16n8k16.row.col.f32.bf16.bf16.f32 "
        "{%0,%1,%2,%3},{%4,%5,%6,%7},{%8,%9},{%0,%1,%2,%3};\n"
        : "+f"(c[0]), "+f"(c[1]), "+f"(c[2]), "+f"(c[3])
        : "r"(a[0]), "r"(a[1]), "r"(a[2]), "r"(a[3]), "r"(b[0]), "r"(b[1]));
}

struct SmemT {
    bf16 A[2][BM][BKP];
    bf16 B[2][BN][BKP];
};

__device__ __forceinline__ void accumulate_pair(
    SmemT& sm,
    const bf16* __restrict__ Ah, const bf16* __restrict__ Al,
    const bf16* __restrict__ Bh, const bf16* __restrict__ Bl, int K,
    int m0, int n0, float (&acc)[2][4][4])
{
    const int tid  = threadIdx.x;
    const int lane = tid & 31;
    const int wid  = tid >> 5;
    const int wm   = wid & 3;
    const int wn   = wid >> 2;
    const int lrow = tid >> 2;
    const int lcol = (tid & 3) * 8;

    const int a_r = wm * 32 + (lane & 15);
    const int a_c = (lane >> 4) * 8;
    const int b_r = wn * 32 + (lane & 7);
    const int b_c = ((lane & 15) >> 3) * 8;

    const bf16* pA  = Ah + (size_t)(m0 + lrow) * K + lcol;
    const bf16* pAl = Al + (size_t)(m0 + lrow) * K + lcol;
    const bf16* pB  = Bh + (size_t)(n0 + lrow) * K + lcol;
    const bf16* pBl = Bl + (size_t)(n0 + lrow) * K + lcol;

    uint4 ra0 = *(const uint4*)pA;
    uint4 ra1 = *(const uint4*)(pA + (size_t)64 * K);
    uint4 rl0 = *(const uint4*)pAl;
    uint4 rl1 = *(const uint4*)(pAl + (size_t)64 * K);
    uint4 rb0 = *(const uint4*)pB;
    uint4 rb1 = *(const uint4*)pBl;

    for (int kc = 0; kc < K; kc += BK) {
        __syncthreads();
        *(uint4*)&sm.A[0][lrow][lcol]      = ra0;
        *(uint4*)&sm.A[0][lrow + 64][lcol] = ra1;
        *(uint4*)&sm.A[1][lrow][lcol]      = rl0;
        *(uint4*)&sm.A[1][lrow + 64][lcol] = rl1;
        *(uint4*)&sm.B[0][lrow][lcol]      = rb0;
        *(uint4*)&sm.B[1][lrow][lcol]      = rb1;
        if (kc + BK < K) {
            pA += BK; pAl += BK; pB += BK; pBl += BK;
            ra0 = *(const uint4*)pA;
            ra1 = *(const uint4*)(pA + (size_t)64 * K);
            rl0 = *(const uint4*)pAl;
            rl1 = *(const uint4*)(pAl + (size_t)64 * K);
            rb0 = *(const uint4*)pB;
            rb1 = *(const uint4*)pBl;
        }
        __syncthreads();
        #pragma unroll
        for (int s = 0; s < 2; s++) {
            uint32_t ah[2][4], alr[2][4], bh[4][2], bl[4][2];
            #pragma unroll
            for (int im = 0; im < 2; im++) {
                ldsm4(ah[im],  (uint32_t)__cvta_generic_to_shared(&sm.A[0][a_r + im*16][a_c + s*16]));
                ldsm4(alr[im], (uint32_t)__cvta_generic_to_shared(&sm.A[1][a_r + im*16][a_c + s*16]));
            }
            #pragma unroll
            for (int in = 0; in < 4; in++) {
                ldsm2(bh[in], (uint32_t)__cvta_generic_to_shared(&sm.B[0][b_r + in*8][b_c + s*16]));
                ldsm2(bl[in], (uint32_t)__cvta_generic_to_shared(&sm.B[1][b_r + in*8][b_c + s*16]));
            }
            #pragma unroll
            for (int im = 0; im < 2; im++)
                #pragma unroll
                for (int in = 0; in < 4; in++) {
                    mma16816(acc[im][in], ah[im],  bh[in]);
                    mma16816(acc[im][in], ah[im],  bl[in]);
                    mma16816(acc[im][in], alr[im], bh[in]);
                }
        }
    }
}

__global__ __launch_bounds__(NT) void gemm3p(
    const bf16* A1h, const bf16* A1l, const bf16* B1h, const bf16* B1l, int K1,
    const bf16* A2h, const bf16* A2l, const bf16* B2h, const bf16* B2l, int K2,
    const float* __restrict__ addv, const float* __restrict__ bias_a,
    const float* __restrict__ bias_b, int do_relu,
    bf16* __restrict__ Oh, bf16* __restrict__ Ol,
    float* __restrict__ Of, int out_mode)
{
    __shared__ SmemT sm;
    float acc[2][4][4];
    #pragma unroll
    for (int i = 0; i < 2; i++)
        #pragma unroll
        for (int j = 0; j < 4; j++)
            #pragma unroll
            for (int k = 0; k < 4; k++) acc[i][j][k] = 0.f;

    const int m0 = blockIdx.y * BM;
    const int n0 = blockIdx.x * BN;

    if (A1h) accumulate_pair(sm, A1h, A1l, B1h, B1l, K1, m0, n0, acc);
    if (A2h) accumulate_pair(sm, A2h, A2l, B2h, B2l, K2, m0, n0, acc);

    const int tid = threadIdx.x, lane = tid & 31, wid = tid >> 5;
    const int wm = wid & 3, wn = wid >> 2;

    #pragma unroll
    for (int im = 0; im < 2; im++)
        #pragma unroll
        for (int in = 0; in < 4; in++) {
            int r0 = m0 + wm * 32 + im * 16 + (lane >> 2);
            int c0 = n0 + wn * 32 + in * 8 + (lane & 3) * 2;
            float v0 = acc[im][in][0], v1 = acc[im][in][1];
            float v2 = acc[im][in][2], v3 = acc[im][in][3];
            if (bias_a) {
                float t0 = bias_a[c0] + bias_b[c0];
                float t1 = bias_a[c0 + 1] + bias_b[c0 + 1];
                v0 += t0; v1 += t1; v2 += t0; v3 += t1;
            }
            if (addv) {
                float2 q0 = *(const float2*)&addv[(size_t)r0 * HH + c0];
                float2 q1 = *(const float2*)&addv[(size_t)(r0 + 8) * HH + c0];
                v0 += q0.x; v1 += q0.y; v2 += q1.x; v3 += q1.y;
            }
            if (do_relu) {
                v0 = fmaxf(v0, 0.f); v1 = fmaxf(v1, 0.f);
                v2 = fmaxf(v2, 0.f); v3 = fmaxf(v3, 0.f);
            }
            if (Oh) {
                bf16 h0 = __float2bfloat16(v0), h1 = __float2bfloat16(v1);
                bf16 h2 = __float2bfloat16(v2), h3 = __float2bfloat16(v3);
                __nv_bfloat162 p;
                p.x = h0; p.y = h1; *(__nv_bfloat162*)&Oh[(size_t)r0 * HH + c0] = p;
                p.x = h2; p.y = h3; *(__nv_bfloat162*)&Oh[(size_t)(r0 + 8) * HH + c0] = p;
                bf16 l0 = __float2bfloat16(v0 - __bfloat162float(h0));
                bf16 l1 = __float2bfloat16(v1 - __bfloat162float(h1));
                bf16 l2 = __float2bfloat16(v2 - __bfloat162float(h2));
                bf16 l3 = __float2bfloat16(v3 - __bfloat162float(h3));
                p.x = l0; p.y = l1; *(__nv_bfloat162*)&Ol[(size_t)r0 * HH + c0] = p;
                p.x = l2; p.y = l3; *(__nv_bfloat162*)&Ol[(size_t)(r0 + 8) * HH + c0] = p;
            }
            if (Of) {
                if (out_mode == 2) {
                    int t  = r0 & (TT - 1), n = r0 >> 5;
                    *(float2*)&Of[((size_t)t * NSEQ + n) * HH + c0] = make_float2(v0, v1);
                    int t2 = (r0 + 8) & (TT - 1), n2 = (r0 + 8) >> 5;
                    *(float2*)&Of[((size_t)t2 * NSEQ + n2) * HH + c0] = make_float2(v2, v3);
                } else {
                    *(float2*)&Of[(size_t)r0 * HH + c0] = make_float2(v0, v1);
                    *(float2*)&Of[(size_t)(r0 + 8) * HH + c0] = make_float2(v2, v3);
                }
            }
        }
}

__global__ void embed_kernel(const int* __restrict__ x, const float* __restrict__ embed) {
    size_t i = (size_t)blockIdx.x * blockDim.x + threadIdx.x;
    size_t r  = i >> 6;
    int    e4 = (int)(i & 63) << 2;
    int tok = x[r];
    float4 v = *(const float4*)(embed + (size_t)tok * EE + e4);
    size_t off = r * EE + e4;
    float vv[4] = {v.x, v.y, v.z, v.w};
    #pragma unroll
    for (int j = 0; j < 4; j++) {
        bf16 h = __float2bfloat16(vv[j]);
        g_Ah[off + j] = h;
        g_Al[off + j] = __float2bfloat16(vv[j] - __bfloat162float(h));
    }
}

__global__ void convert_weights(const float* __restrict__ w0, const float* __restrict__ w1,
                                const float* __restrict__ w2, const float* __restrict__ w3) {
    int i = blockIdx.x * 256 + threadIdx.x;
    if (i >= WTOT) return;
    float v;
    if      (i < OFF_HH0) v = w0[i - OFF_IH0];
    else if (i < OFF_IH1) v = w1[i - OFF_HH0];
    else if (i < OFF_HH1) v = w2[i - OFF_IH1];
    else                  v = w3[i - OFF_HH1];
    bf16 h = __float2bfloat16(v);
    g_Wh[i] = h;
    g_Wl[i] = __float2bfloat16(v - __bfloat162float(h));
}

__global__ void final_kernel(const float* __restrict__ h1, const float* __restrict__ Wp,
                             const float* __restrict__ bp, float* __restrict__ out) {
    __shared__ float wc[1024];
    __shared__ float red[256];
    __shared__ float ctermS;
    int b = blockIdx.x, tid = threadIdx.x;
    const float* Hb = h1 + (size_t)b * 256 * HH;
    float s0 = 0.f, s1 = 0.f;
    for (int cell = 0; cell < 256; cell++) {
        const float* row = Hb + (size_t)cell * HH;
        s0 += row[tid];
        s1 += row[tid + 256];
    }
    wc[tid]       = Wp[tid]       - Wp[HH + tid];
    wc[tid + 256] = Wp[tid + 256] - Wp[HH + tid + 256];
    red[tid] = s0 * Wp[HH + tid] + s1 * Wp[HH + tid + 256];
    __syncthreads();
    for (int s = 128; s > 0; s >>= 1) {
        if (tid < s) red[tid] += red[tid + s];
        __syncthreads();
    }
    if (tid == 0) ctermS = red[0] + bp[0];
    __syncthreads();
    int warp = tid >> 5, lane = tid & 31;
    for (int cell = warp; cell < 256; cell += 8) {
        const float* row = Hb + (size_t)cell * HH;
        float a = 0.f;
        for (int c = lane; c < HH; c += 32) a += row[c] * wc[c];
        #pragma unroll
        for (int o = 16; o; o >>= 1) a += __shfl_xor_sync(0xffffffffu, a, o);
        if (lane == 0) out[(size_t)b * 256 + cell] = a + ctermS;
    }
}

extern "C" void kernel_launch(void* const* d_in, const int* in_sizes, int n_in,
                              void* d_out, int out_size) {
    (void)in_sizes; (void)n_in; (void)out_size;
    const int*   x      = (const int*)  d_in[0];
    const float* embedp = (const float*)d_in[1];
    const float* W_ih0  = (const float*)d_in[2];
    const float* W_hh0  = (const float*)d_in[3];
    const float* b_ih0  = (const float*)d_in[4];
    const float* b_hh0  = (const float*)d_in[5];
    const float* W_ih1  = (const float*)d_in[6];
    const float* W_hh1  = (const float*)d_in[7];
    const float* b_ih1  = (const float*)d_in[8];
    const float* b_hh1  = (const float*)d_in[9];
    const float* W_pred = (const float*)d_in[10];
    const float* b_pred = (const float*)d_in[11];
    float* out = (float*)d_out;

    bf16 *Ah, *Al, *Wh, *Wl;
    bf16 (*h0h)[(size_t)NSEQ * HH], (*h0l)[(size_t)NSEQ * HH];
    bf16 (*h1h)[(size_t)NSEQ * HH], (*h1l)[(size_t)NSEQ * HH];
    float *pre0, *h1f;
    cudaGetSymbolAddress((void**)&Ah,  g_Ah);
    cudaGetSymbolAddress((void**)&Al,  g_Al);
    cudaGetSymbolAddress((void**)&Wh,  g_Wh);
    cudaGetSymbolAddress((void**)&Wl,  g_Wl);
    cudaGetSymbolAddress((void**)&h0h, g_h0h);
    cudaGetSymbolAddress((void**)&h0l, g_h0l);
    cudaGetSymbolAddress((void**)&h1h, g_h1h);
    cudaGetSymbolAddress((void**)&h1l, g_h1l);
    cudaGetSymbolAddress((void**)&pre0, g_pre0);
    cudaGetSymbolAddress((void**)&h1f,  g_h1f);

    convert_weights<<<(WTOT + 255) / 256, 256>>>(W_ih0, W_hh0, W_ih1, W_hh1);
    embed_kernel<<<(MROWS * EE / 4 + 255) / 256, 256>>>(x, embedp);

    // pre0 = emb @ W_ih0^T + b_ih0 + b_hh0, scattered to [t][n][h]
    gemm3p<<<dim3(HH / BN, MROWS / BM), NT>>>(
        Ah, Al, Wh + OFF_IH0, Wl + OFF_IH0, EE,
        nullptr, nullptr, nullptr, nullptr, 0,
        nullptr, b_ih0, b_hh0, 0,
        nullptr, nullptr, pre0, 2);

    dim3 rg(HH / BN, NSEQ / BM);
    for (int t = 0; t < TT; t++) {
        int rd = t & 1, wr = rd ^ 1;
        // layer 0: h0_t = relu(pre0[t] + h0_{t-1} @ W_hh0^T)
        gemm3p<<<rg, NT>>>(
            (t ? h0h[rd] : nullptr), (t ? h0l[rd] : nullptr),
            Wh + OFF_HH0, Wl + OFF_HH0, HH,
            nullptr, nullptr, nullptr, nullptr, 0,
            pre0 + (size_t)t * NSEQ * HH, nullptr, nullptr, 1,
            h0h[wr], h0l[wr], nullptr, 0);
        // layer 1: h1_t = relu(h0_t @ W_ih1^T + h1_{t-1} @ W_hh1^T + b_ih1 + b_hh1)
        gemm3p<<<rg, NT>>>(
            h0h[wr], h0l[wr], Wh + OFF_IH1, Wl + OFF_IH1, HH,
            (t ? h1h[rd] : nullptr), (t ? h1l[rd] : nullptr),
            Wh + OFF_HH1, Wl + OFF_HH1, HH,
            nullptr, b_ih1, b_hh1, 1,
            h1h[wr], h1l[wr], (t == TT - 1 ? h1f : nullptr), 1);
    }

    final_kernel<<<8, 256>>>(h1f, W_pred, b_pred, out);
}